// round 1
// baseline (speedup 1.0000x reference)
#include <cuda_runtime.h>

// ContourIntegrationLayer: depthwise 3x3 conv (center tap zeroed) + residual.
// x: [B=32, H=56, W=56, C=256] fp32 NHWC, kernel: [3,3,256] fp32.
// Residual folded in by forcing the center weight to 1.0.
//
// Block: threadIdx.x = channel-group (8 float4 = 32 channels),
//        threadIdx.y = w-pair (28 pairs -> W=56).
// Grid:  256 blocks = 32 batches x 8 channel-blocks, all resident (occ 2/SM).
// SMEM:  4-slot row ring, each row 58 padded columns (zero halo) x 8 float4.

#define B_ 32
#define H_ 56
#define W_ 56
#define C_ 256
#define CG 8                 // float4 channel groups per block (32 channels)
#define CBLK (C_ / (CG * 4)) // 8 channel blocks

__global__ __launch_bounds__(224, 2)
void contour_kernel(const float4* __restrict__ x,
                    const float*  __restrict__ krn,
                    float4*       __restrict__ out)
{
    const int tx = threadIdx.x;          // 0..7  channel group
    const int ty = threadIdx.y;          // 0..27 w-pair
    const int bc = blockIdx.x;
    const int b  = bc >> 3;              // batch
    const int cb = bc & 7;               // channel block
    const int c  = cb * 32 + tx * 4;     // first channel of this thread

    __shared__ float4 s[4][58][CG];      // [slot][w+1][cgroup], 29696 B

    // ---- load 3x3 per-channel weights; center tap := 1.0 (residual fold) ----
    float4 Wt[3][3];
#pragma unroll
    for (int ky = 0; ky < 3; ky++)
#pragma unroll
        for (int kx = 0; kx < 3; kx++)
            Wt[ky][kx] = *reinterpret_cast<const float4*>(krn + (ky * 3 + kx) * C_ + c);
    Wt[1][1] = make_float4(1.f, 1.f, 1.f, 1.f);

    const int w0 = ty * 2;
    const int w1 = w0 + 1;
    const size_t rowstride = (size_t)W_ * (C_ / 4);          // float4 per row
    const float4* xb = x   + (size_t)b * H_ * rowstride + cb * CG + tx;
    float4*       ob = out + (size_t)b * H_ * rowstride + cb * CG + tx;

    const float4 z = make_float4(0.f, 0.f, 0.f, 0.f);

    // zero halo columns for all 4 slots (never overwritten afterwards)
    if (ty == 0) {
#pragma unroll
        for (int sl = 0; sl < 4; sl++) { s[sl][0][tx] = z; s[sl][57][tx] = z; }
    }

    // LDG one row's two pixels into registers (zeros if out of range)
    auto fetch = [&](int r, float4& v0, float4& v1) {
        v0 = z; v1 = z;
        if ((unsigned)r < (unsigned)H_) {
            const float4* p = xb + (size_t)r * rowstride;
            v0 = p[(size_t)w0 * (C_ / 4)];
            v1 = p[(size_t)w1 * (C_ / 4)];
        }
    };
    auto sts_row = [&](int r, const float4& v0, const float4& v1) {
        int sl = r & 3;                       // row r lives in slot r mod 4 (-1 -> 3)
        s[sl][w0 + 1][tx] = v0;
        s[sl][w1 + 1][tx] = v1;
    };

    // preload rows -1 (zeros), 0, 1
    {
        float4 a, b2;
        fetch(-1, a, b2); sts_row(-1, a, b2);
        fetch(0,  a, b2); sts_row(0,  a, b2);
        fetch(1,  a, b2); sts_row(1,  a, b2);
    }
    // prefetch row 2 into registers
    float4 p0, p1;
    fetch(2, p0, p1);
    __syncthreads();

    for (int h = 0; h < H_; h++) {
        const int sm = (h - 1) & 3, sc = h & 3, sp = (h + 1) & 3;
        float4 a0 = z, a1 = z;
        const int slots[3] = {sm, sc, sp};
#pragma unroll
        for (int ky = 0; ky < 3; ky++) {
            const int sl = slots[ky];
            const float4 v0 = s[sl][w0    ][tx];
            const float4 v1 = s[sl][w0 + 1][tx];
            const float4 v2 = s[sl][w0 + 2][tx];
            const float4 v3 = s[sl][w0 + 3][tx];
            const float4 k0 = Wt[ky][0], k1 = Wt[ky][1], k2 = Wt[ky][2];

            a0.x = fmaf(k0.x, v0.x, fmaf(k1.x, v1.x, fmaf(k2.x, v2.x, a0.x)));
            a0.y = fmaf(k0.y, v0.y, fmaf(k1.y, v1.y, fmaf(k2.y, v2.y, a0.y)));
            a0.z = fmaf(k0.z, v0.z, fmaf(k1.z, v1.z, fmaf(k2.z, v2.z, a0.z)));
            a0.w = fmaf(k0.w, v0.w, fmaf(k1.w, v1.w, fmaf(k2.w, v2.w, a0.w)));

            a1.x = fmaf(k0.x, v1.x, fmaf(k1.x, v2.x, fmaf(k2.x, v3.x, a1.x)));
            a1.y = fmaf(k0.y, v1.y, fmaf(k1.y, v2.y, fmaf(k2.y, v3.y, a1.y)));
            a1.z = fmaf(k0.z, v1.z, fmaf(k1.z, v2.z, fmaf(k2.z, v3.z, a1.z)));
            a1.w = fmaf(k0.w, v1.w, fmaf(k1.w, v2.w, fmaf(k2.w, v3.w, a1.w)));
        }

        float4* po = ob + (size_t)h * rowstride;
        po[(size_t)w0 * (C_ / 4)] = a0;
        po[(size_t)w1 * (C_ / 4)] = a1;

        // stage prefetched row h+2 into its slot ((h+2)&3 — disjoint from read slots)
        sts_row(h + 2, p0, p1);
        // issue LDG for row h+3 (consumed next iteration's sts)
        fetch(h + 3, p0, p1);
        __syncthreads();
    }
}

extern "C" void kernel_launch(void* const* d_in, const int* in_sizes, int n_in,
                              void* d_out, int out_size)
{
    const float4* x   = (const float4*)d_in[0];
    const float*  krn = (const float*)d_in[1];
    float4*       out = (float4*)d_out;

    dim3 block(CG, W_ / 2, 1);         // 8 x 28 = 224 threads
    dim3 grid(B_ * CBLK, 1, 1);        // 256 blocks
    contour_kernel<<<grid, block>>>(x, krn, out);
}

// round 2
// speedup vs baseline: 1.2746x; 1.2746x over previous
#include <cuda_runtime.h>

// ContourIntegrationLayer: depthwise 3x3 conv (center tap zeroed) + residual.
// x: [B=32, H=56, W=56, C=256] fp32 NHWC, kernel: [3,3,256] fp32.
// Residual folded by forcing the center weight to 1.0.
//
// Sync-free register-accumulator design:
//   each input row is loaded ONCE (4x LDG.128/thread: cols w0-1..w1+1) and its
//   three horizontal convolutions are accumulated into ring accumulators for
//   output rows r-1, r, r+1. No shared memory, no __syncthreads.
// Block: (8 channel-float4, 28 w-pairs) = 224 threads.
// Grid:  8 channel-blocks x 4 H-chunks x 32 batches = 1024 blocks.

#define B_  32
#define H_  56
#define W_  56
#define C_  256
#define CG  8
#define HC  14                   // output rows per block
#define CQ  (C_ / 4)             // 64 float4 per pixel
#define ROWF4 (W_ * CQ)          // 3584 float4 per image row

__global__ __launch_bounds__(224, 2)
void contour_kernel(const float4* __restrict__ x,
                    const float*  __restrict__ krn,
                    float4*       __restrict__ out)
{
    const int tx  = threadIdx.x;     // 0..7  channel group
    const int ty  = threadIdx.y;     // 0..27 w-pair
    const int cb  = blockIdx.x;      // 0..7  channel block
    const int hch = blockIdx.y;      // 0..3  H chunk
    const int b   = blockIdx.z;      // 0..31 batch
    const int c   = cb * 32 + tx * 4;

    // 3x3 per-channel weights; center tap := 1.0 (residual fold)
    float4 Wt[3][3];
#pragma unroll
    for (int ky = 0; ky < 3; ky++)
#pragma unroll
        for (int kx = 0; kx < 3; kx++)
            Wt[ky][kx] = *reinterpret_cast<const float4*>(krn + (ky * 3 + kx) * C_ + c);
    Wt[1][1] = make_float4(1.f, 1.f, 1.f, 1.f);

    const int  w0  = ty * 2;
    const bool wlo = (w0 > 0);           // col w0-1 exists
    const bool whi = (w0 + 2 < W_);      // col w1+1 exists
    const float4 z = make_float4(0.f, 0.f, 0.f, 0.f);

    const size_t base = (size_t)b * H_ * ROWF4 + (size_t)w0 * CQ + cb * CG + tx;
    const float4* xb = x   + base;
    float4*       ob = out + base;

    const int hs = hch * HC;

    // --- row loader: cols w0-1, w0, w0+1, w0+2 of input row r (zeros OOB) ---
    auto load = [&](int r, float4& v0, float4& v1, float4& v2, float4& v3) {
        if ((unsigned)r < (unsigned)H_) {
            const float4* p = xb + (size_t)r * ROWF4;
            v0 = wlo ? p[-CQ]    : z;
            v1 = p[0];
            v2 = p[CQ];
            v3 = whi ? p[2 * CQ] : z;
        } else {
            v0 = z; v1 = z; v2 = z; v3 = z;
        }
    };

    // horizontal conv of (v0..v3) with weight row k, accumulated into (o0,o1)
    auto hconv = [&](float4& o0, float4& o1, const float4 k0, const float4 k1,
                     const float4 k2, const float4 v0, const float4 v1,
                     const float4 v2, const float4 v3) {
        o0.x = fmaf(k0.x, v0.x, fmaf(k1.x, v1.x, fmaf(k2.x, v2.x, o0.x)));
        o0.y = fmaf(k0.y, v0.y, fmaf(k1.y, v1.y, fmaf(k2.y, v2.y, o0.y)));
        o0.z = fmaf(k0.z, v0.z, fmaf(k1.z, v1.z, fmaf(k2.z, v2.z, o0.z)));
        o0.w = fmaf(k0.w, v0.w, fmaf(k1.w, v1.w, fmaf(k2.w, v2.w, o0.w)));
        o1.x = fmaf(k0.x, v1.x, fmaf(k1.x, v2.x, fmaf(k2.x, v3.x, o1.x)));
        o1.y = fmaf(k0.y, v1.y, fmaf(k1.y, v2.y, fmaf(k2.y, v3.y, o1.y)));
        o1.z = fmaf(k0.z, v1.z, fmaf(k1.z, v2.z, fmaf(k2.z, v3.z, o1.z)));
        o1.w = fmaf(k0.w, v1.w, fmaf(k1.w, v2.w, fmaf(k2.w, v3.w, o1.w)));
    };

    float4 c0, c1, c2, c3;          // current input row
    float4 n0, n1, n2, n3;          // prefetched next input row
    float4 am0 = z, am1 = z;        // partial accum for output row r-1
    float4 ac0 = z, ac1 = z;        // partial accum for output row r

    load(hs - 1, c0, c1, c2, c3);   // first input row
    load(hs,     n0, n1, n2, n3);   // prefetch second

    // iterations i=0..HC+1 process input rows hs-1 .. hs+HC
#pragma unroll
    for (int i = 0; i < HC + 2; i++) {
        const int r = hs - 1 + i;

        // complete output row r-1 with this row's bottom-tap contribution
        float4 d0 = am0, d1 = am1;
        hconv(d0, d1, Wt[2][0], Wt[2][1], Wt[2][2], c0, c1, c2, c3);
        if (i >= 2) {               // output rows hs .. hs+HC-1
            float4* po = ob + (size_t)(r - 1) * ROWF4;
            po[0]  = d0;
            po[CQ] = d1;
        }

        // roll accumulators: am <- ac + middle-tap, ac <- top-tap (fresh)
        am0 = ac0; am1 = ac1;
        hconv(am0, am1, Wt[1][0], Wt[1][1], Wt[1][2], c0, c1, c2, c3);
        ac0 = z; ac1 = z;
        hconv(ac0, ac1, Wt[0][0], Wt[0][1], Wt[0][2], c0, c1, c2, c3);

        // shift in prefetched row, issue next prefetch
        c0 = n0; c1 = n1; c2 = n2; c3 = n3;
        if (i <= HC - 1)
            load(r + 2, n0, n1, n2, n3);
    }
}

extern "C" void kernel_launch(void* const* d_in, const int* in_sizes, int n_in,
                              void* d_out, int out_size)
{
    const float4* x   = (const float4*)d_in[0];
    const float*  krn = (const float*)d_in[1];
    float4*       out = (float4*)d_out;

    dim3 block(CG, W_ / 2, 1);               // 224 threads
    dim3 grid(C_ / (CG * 4), H_ / HC, B_);   // 8 x 4 x 32 = 1024 blocks
    contour_kernel<<<grid, block>>>(x, krn, out);
}

// round 3
// speedup vs baseline: 1.3929x; 1.0929x over previous
#include <cuda_runtime.h>

// ContourIntegrationLayer: depthwise 3x3 conv (center tap zeroed) + residual.
// x: [B=32, H=56, W=56, C=256] fp32 NHWC, kernel: [3,3,256] fp32.
// Residual folded by forcing the center weight to 1.0.
//
// Sync-free register-accumulator design with a 3-slot register ring:
//   row r's 4x LDG.128 are issued at iteration i and consumed at i+3 -> two
//   full rows (8 LDG.128/thread) in flight, no register moves, no waits
//   before actual consumption. No shared memory, no __syncthreads.
// Block: (8 channel-float4, 28 w-pairs) = 224 threads.
// Grid:  8 channel-blocks x 4 H-chunks x 32 batches = 1024 blocks.

#define B_  32
#define H_  56
#define W_  56
#define C_  256
#define CG  8
#define HC  14                   // output rows per block
#define CQ  (C_ / 4)             // 64 float4 per pixel
#define ROWF4 (W_ * CQ)          // 3584 float4 per image row

__global__ __launch_bounds__(224, 2)
void contour_kernel(const float4* __restrict__ x,
                    const float*  __restrict__ krn,
                    float4*       __restrict__ out)
{
    const int tx  = threadIdx.x;     // 0..7  channel group
    const int ty  = threadIdx.y;     // 0..27 w-pair
    const int cb  = blockIdx.x;      // 0..7  channel block
    const int hch = blockIdx.y;      // 0..3  H chunk
    const int b   = blockIdx.z;      // 0..31 batch
    const int c   = cb * 32 + tx * 4;

    // 3x3 per-channel weights; center tap := 1.0 (residual fold)
    float4 Wt[3][3];
#pragma unroll
    for (int ky = 0; ky < 3; ky++)
#pragma unroll
        for (int kx = 0; kx < 3; kx++)
            Wt[ky][kx] = *reinterpret_cast<const float4*>(krn + (ky * 3 + kx) * C_ + c);
    Wt[1][1] = make_float4(1.f, 1.f, 1.f, 1.f);

    const int  w0  = ty * 2;
    const bool wlo = (w0 > 0);           // col w0-1 exists
    const bool whi = (w0 + 2 < W_);      // col w1+1 exists
    const float4 z = make_float4(0.f, 0.f, 0.f, 0.f);

    const size_t base = (size_t)b * H_ * ROWF4 + (size_t)w0 * CQ + cb * CG + tx;
    const float4* xb = x   + base;
    float4*       ob = out + base;

    const int hs = hch * HC;

    // row loader: cols w0-1, w0, w0+1, w0+2 of input row r (zeros OOB)
    auto load = [&](int r, float4* v) {
        if ((unsigned)r < (unsigned)H_) {
            const float4* p = xb + (size_t)r * ROWF4;
            v[0] = wlo ? p[-CQ]    : z;
            v[1] = p[0];
            v[2] = p[CQ];
            v[3] = whi ? p[2 * CQ] : z;
        } else {
            v[0] = z; v[1] = z; v[2] = z; v[3] = z;
        }
    };

    // horizontal conv of v[0..3] with weight row k, accumulated into (o0,o1)
    auto hconv = [&](float4& o0, float4& o1, const float4 k0, const float4 k1,
                     const float4 k2, const float4* v) {
        o0.x = fmaf(k0.x, v[0].x, fmaf(k1.x, v[1].x, fmaf(k2.x, v[2].x, o0.x)));
        o0.y = fmaf(k0.y, v[0].y, fmaf(k1.y, v[1].y, fmaf(k2.y, v[2].y, o0.y)));
        o0.z = fmaf(k0.z, v[0].z, fmaf(k1.z, v[1].z, fmaf(k2.z, v[2].z, o0.z)));
        o0.w = fmaf(k0.w, v[0].w, fmaf(k1.w, v[1].w, fmaf(k2.w, v[2].w, o0.w)));
        o1.x = fmaf(k0.x, v[1].x, fmaf(k1.x, v[2].x, fmaf(k2.x, v[3].x, o1.x)));
        o1.y = fmaf(k0.y, v[1].y, fmaf(k1.y, v[2].y, fmaf(k2.y, v[3].y, o1.y)));
        o1.z = fmaf(k0.z, v[1].z, fmaf(k1.z, v[2].z, fmaf(k2.z, v[3].z, o1.z)));
        o1.w = fmaf(k0.w, v[1].w, fmaf(k1.w, v[2].w, fmaf(k2.w, v[3].w, o1.w)));
    };

    float4 buf[3][4];               // 3-slot register row ring
    float4 am0 = z, am1 = z;        // partial accum for output row r-1
    float4 ac0 = z, ac1 = z;        // partial accum for output row r

    // prolog: rows hs-1, hs, hs+1 into slots 0,1,2 (all loads issued back-to-back)
    load(hs - 1, buf[0]);
    load(hs,     buf[1]);
    load(hs + 1, buf[2]);

    // iterations i = 0..HC+1 consume input rows hs-1 .. hs+HC
#pragma unroll
    for (int i = 0; i < HC + 2; i++) {
        const int r = hs - 1 + i;
        const float4* cur = buf[i % 3];

        // complete output row r-1 with this row's bottom-tap contribution
        float4 d0 = am0, d1 = am1;
        hconv(d0, d1, Wt[2][0], Wt[2][1], Wt[2][2], cur);
        if (i >= 2) {               // output rows hs .. hs+HC-1
            float4* po = ob + (size_t)(r - 1) * ROWF4;
            po[0]  = d0;
            po[CQ] = d1;
        }

        // roll accumulators: am <- ac + middle-tap, ac <- top-tap (fresh)
        am0 = ac0; am1 = ac1;
        hconv(am0, am1, Wt[1][0], Wt[1][1], Wt[1][2], cur);
        ac0 = z; ac1 = z;
        hconv(ac0, ac1, Wt[0][0], Wt[0][1], Wt[0][2], cur);

        // refill the slot just consumed with row r+3 (consumed at i+3)
        if (i <= HC - 2)
            load(r + 3, buf[i % 3]);
    }
}

extern "C" void kernel_launch(void* const* d_in, const int* in_sizes, int n_in,
                              void* d_out, int out_size)
{
    const float4* x   = (const float4*)d_in[0];
    const float*  krn = (const float*)d_in[1];
    float4*       out = (float4*)d_out;

    dim3 block(CG, W_ / 2, 1);               // 224 threads
    dim3 grid(C_ / (CG * 4), H_ / HC, B_);   // 8 x 4 x 32 = 1024 blocks
    contour_kernel<<<grid, block>>>(x, krn, out);
}